// round 14
// baseline (speedup 1.0000x reference)
#include <cuda_runtime.h>
#include <cuda_bf16.h>
#include <math.h>
#include <stdint.h>

#define B_   128
#define T_   512
#define DIN  256
#define DH   1024
#define DOUT 1024
#define BDH  (B_*DH)            /* 131072 */
#define OROW ((T_+1)*DOUT)      /* 525312 */
#define SCTA 128                /* persistent scan CTAs */

/* ------------------------------------------------------------------ */
/* Scratch (device globals: allocation-free rule)                      */
/* ------------------------------------------------------------------ */
__device__ float         g_xs  [(size_t)T_ * B_ * DH];   /* xs + Wx_b fp32  256MB */
__device__ __nv_bfloat16 g_shi [(size_t)T_ * B_ * DH];   /* s hi split      128MB */
__device__ __nv_bfloat16 g_slo [(size_t)T_ * B_ * DH];   /* s lo split      128MB */
__device__ __nv_bfloat16 g_seqhi[(size_t)B_ * T_ * DIN];
__device__ __nv_bfloat16 g_seqlo[(size_t)B_ * T_ * DIN];
__device__ __nv_bfloat16 g_wohi[(size_t)DOUT * DH];
__device__ __nv_bfloat16 g_wolo[(size_t)DOUT * DH];
__device__ __nv_bfloat16 g_wxhi[(size_t)DH * DIN];
__device__ __nv_bfloat16 g_wxlo[(size_t)DH * DIN];
__device__ __nv_bfloat16 g_hhi[2][BDH];       /* hidden state hi, ping-pong */
__device__ __nv_bfloat16 g_hlo[2][BDH];       /* hidden state lo            */
__device__ unsigned int g_cnt = 0;
__device__ unsigned int g_gen = 0;

/* ------------------------------------------------------------------ */
/* PTX helpers (all baseline ISA: valid for compute_103 / sm_103)      */
/* ------------------------------------------------------------------ */
__device__ __forceinline__ uint32_t smem_u32(const void* p) {
    uint32_t a;
    asm("{ .reg .u64 t; cvta.to.shared.u64 t, %1; cvt.u32.u64 %0, t; }"
        : "=r"(a) : "l"(p));
    return a;
}
__device__ __forceinline__ void ldsm4(uint32_t* r, uint32_t addr) {
    asm volatile("ldmatrix.sync.aligned.m8n8.x4.shared.b16 {%0,%1,%2,%3}, [%4];"
        : "=r"(r[0]), "=r"(r[1]), "=r"(r[2]), "=r"(r[3]) : "r"(addr));
}
__device__ __forceinline__ void mma16816(float* d, const uint32_t* a,
                                         const uint32_t* b) {
    asm volatile(
        "mma.sync.aligned.m16n8k16.row.col.f32.bf16.bf16.f32 "
        "{%0,%1,%2,%3}, {%4,%5,%6,%7}, {%8,%9}, {%0,%1,%2,%3};"
        : "+f"(d[0]), "+f"(d[1]), "+f"(d[2]), "+f"(d[3])
        : "r"(a[0]), "r"(a[1]), "r"(a[2]), "r"(a[3]), "r"(b[0]), "r"(b[1]));
}
#define CP16(dst, src) \
    asm volatile("cp.async.cg.shared.global [%0], [%1], 16;" :: "r"(dst), "l"(src))
#define CP_COMMIT()  asm volatile("cp.async.commit_group;" ::: "memory")
#define CP_WAIT0()   asm volatile("cp.async.wait_group 0;" ::: "memory")
#define CP_WAIT1()   asm volatile("cp.async.wait_group 1;" ::: "memory")

/* ------------------------------------------------------------------ */
__global__ void zero_front(float* __restrict__ out)
{
    int idx = blockIdx.x * blockDim.x + threadIdx.x;   /* 0 .. 131071 */
    int b = idx >> 10;
    int j = idx & 1023;
    out[(size_t)b * OROW + j] = 0.0f;
}

/* hi/lo bf16 split conversions */
__device__ __forceinline__ void split1(float x, __nv_bfloat16* hi, __nv_bfloat16* lo)
{
    __nv_bfloat16 h = __float2bfloat16(x);
    *hi = h;
    *lo = __float2bfloat16(x - __bfloat162float(h));
}
__global__ void conv_seq(const float* __restrict__ src)
{
    size_t i = (size_t)blockIdx.x * blockDim.x + threadIdx.x;
    if (i < (size_t)B_ * T_ * DIN) split1(src[i], &g_seqhi[i], &g_seqlo[i]);
}
__global__ void conv_wo(const float* __restrict__ src)
{
    size_t i = (size_t)blockIdx.x * blockDim.x + threadIdx.x;
    if (i < (size_t)DOUT * DH) split1(src[i], &g_wohi[i], &g_wolo[i]);
}
__global__ void conv_wx(const float* __restrict__ src)
{
    size_t i = (size_t)blockIdx.x * blockDim.x + threadIdx.x;
    if (i < (size_t)DH * DIN) split1(src[i], &g_wxhi[i], &g_wxlo[i]);
}

/* ------------------------------------------------------------------ */
/* mma.sync GEMM (unchanged, proven):                                  */
/* MODE 0: xs  = seq @ Wx^T + bx   (K=256)  -> g_xs fp32               */
/* MODE 1: out = s   @ Wo^T + bo   (K=1024) -> scattered into d_out    */
/* ------------------------------------------------------------------ */
template<int MODE>
__global__ __launch_bounds__(256) void wm_gemm(const float* __restrict__ bias,
                                               float* __restrict__ outp)
{
    constexpr int K  = (MODE == 0) ? DIN : DH;
    constexpr int NC = K / 64;

    extern __shared__ char sm[];
    const uint32_t smb = (smem_u32(sm) + 1023u) & ~1023u;

    const int tid  = threadIdx.x;
    const int lane = tid & 31;
    const int w    = tid >> 5;
    const int wm   = w & 3;
    const int wn   = w >> 2;
    const int n0   = blockIdx.x * 128;
    const int tY   = blockIdx.y;
    const int m0   = tY * 128;

    const __nv_bfloat16* Ahi_g;
    const __nv_bfloat16* Alo_g;
    const __nv_bfloat16* Bhi_g;
    const __nv_bfloat16* Blo_g;
    if (MODE == 0) { Ahi_g = g_seqhi; Alo_g = g_seqlo; Bhi_g = g_wxhi; Blo_g = g_wxlo; }
    else           { Ahi_g = g_shi;   Alo_g = g_slo;   Bhi_g = g_wohi; Blo_g = g_wolo; }

#define LOAD_CHUNK(cc, bb_) do {                                            \
    uint32_t _db = smb + (uint32_t)(bb_) * 65536u;                          \
    _Pragma("unroll")                                                       \
    for (int _i = 0; _i < 16; _i++) {                                       \
        int _tile = _i >> 2;                                                \
        int _r    = (_i & 3) * 32 + (tid >> 3);                             \
        int _c16  = tid & 7;                                                \
        uint32_t _dst = _db + (uint32_t)_tile * 16384u + (uint32_t)_r * 128u\
                      + (uint32_t)((_c16 ^ (_r & 7)) << 4);                 \
        const __nv_bfloat16* _src;                                          \
        if (_tile == 0 || _tile == 1) {                                     \
            const __nv_bfloat16* _A = (_tile == 0) ? Ahi_g : Alo_g;         \
            if (MODE == 0)                                                  \
                _src = _A + ((size_t)_r * T_ + tY) * DIN + _c16 * 8 + (cc) * 64; \
            else                                                            \
                _src = _A + (size_t)(m0 + _r) * DH + _c16 * 8 + (cc) * 64;  \
        } else {                                                            \
            const __nv_bfloat16* _B = (_tile == 2) ? Bhi_g : Blo_g;         \
            _src = _B + (size_t)(n0 + _r) * K + _c16 * 8 + (cc) * 64;       \
        }                                                                   \
        CP16(_dst, _src);                                                   \
    }                                                                       \
    CP_COMMIT();                                                            \
} while (0)

    const int arow = wm * 32 + (lane & 15);
    const int axor = arow & 7;
    const int ahlf = lane >> 4;
    const int brow = wn * 64 + ((lane >> 4) & 1) * 8 + (lane & 7);
    const int bxor = brow & 7;
    const int bhlf = (lane >> 3) & 1;

    float d[64];
#pragma unroll
    for (int i = 0; i < 64; i++) d[i] = 0.f;

    LOAD_CHUNK(0, 0);

    for (int c = 0; c < NC; c++) {
        if (c + 1 < NC) LOAD_CHUNK(c + 1, (c + 1) & 1);
        if (c + 1 < NC) CP_WAIT1(); else CP_WAIT0();
        __syncthreads();

        const uint32_t db = smb + (uint32_t)(c & 1) * 65536u;
#pragma unroll
        for (int k16 = 0; k16 < 4; k16++) {
            uint32_t ahi[8], alo[8], bb[16];
            const uint32_t ao = db + (uint32_t)arow * 128u
                              + (uint32_t)(((k16 * 2 + ahlf) ^ axor) << 4);
            ldsm4(ahi,     ao);
            ldsm4(ahi + 4, ao + 2048u);
            const uint32_t bo = db + 32768u + (uint32_t)brow * 128u
                              + (uint32_t)(((k16 * 2 + bhlf) ^ bxor) << 4);
#pragma unroll
            for (int p = 0; p < 4; p++) ldsm4(bb + p * 4, bo + (uint32_t)p * 2048u);
#pragma unroll
            for (int t = 0; t < 2; t++)
#pragma unroll
                for (int q = 0; q < 8; q++)
                    mma16816(d + (t * 8 + q) * 4, ahi + t * 4, bb + q * 2);

            ldsm4(alo,     ao + 16384u);
            ldsm4(alo + 4, ao + 16384u + 2048u);
#pragma unroll
            for (int t = 0; t < 2; t++)
#pragma unroll
                for (int q = 0; q < 8; q++)
                    mma16816(d + (t * 8 + q) * 4, alo + t * 4, bb + q * 2);

#pragma unroll
            for (int p = 0; p < 4; p++)
                ldsm4(bb + p * 4, bo + 16384u + (uint32_t)p * 2048u);
#pragma unroll
            for (int t = 0; t < 2; t++)
#pragma unroll
                for (int q = 0; q < 8; q++)
                    mma16816(d + (t * 8 + q) * 4, ahi + t * 4, bb + q * 2);
        }
        __syncthreads();
    }

    const int rl = lane >> 2;
    const int lc = (lane & 3) * 2;
#pragma unroll
    for (int t = 0; t < 2; t++)
#pragma unroll
        for (int q = 0; q < 8; q++) {
            int col = n0 + wn * 64 + q * 8 + lc;
            float b0v = __ldg(bias + col), b1v = __ldg(bias + col + 1);
            float* dd = d + (t * 8 + q) * 4;
            int r0 = wm * 32 + t * 16 + rl;
            if (MODE == 0) {
                *(float2*)(g_xs + (size_t)(m0 + r0) * DH + col) =
                    make_float2(dd[0] + b0v, dd[1] + b1v);
                *(float2*)(g_xs + (size_t)(m0 + r0 + 8) * DH + col) =
                    make_float2(dd[2] + b0v, dd[3] + b1v);
            } else {
                *(float2*)(outp + (size_t)r0 * OROW + (size_t)(tY + 1) * DOUT + col) =
                    make_float2(dd[0] + b0v, dd[1] + b1v);
                *(float2*)(outp + (size_t)(r0 + 8) * OROW + (size_t)(tY + 1) * DOUT + col) =
                    make_float2(dd[2] + b0v, dd[3] + b1v);
            }
        }
#undef LOAD_CHUNK
}

/* ------------------------------------------------------------------ */
/* Persistent tensorized scan, v2 (ring-slot fix: chunk 3 -> slot 0).  */
/*  - 3 independent accumulators (break HMMA RAW chain)                */
/*  - k=256 chunks, 3-stage cp.async ring -> 4 syncthreads/step        */
/*  - B hi+lo fused into one ldsm4 (lane-split whHi/whLo)              */
/*  - xs prefetched at step start; split-phase grid barrier with       */
/*    s hi/lo stores inside the wait window                            */
/* SMEM: Wh hi 64KB | Wh lo 64KB | 3 x 32KB H ring = 224KB             */
/* ------------------------------------------------------------------ */
__global__ __launch_bounds__(256) void scan_mma(const float* __restrict__ Wh,
                                                const float* __restrict__ bh)
{
    extern __shared__ char sm[];
    const uint32_t smb0 = smem_u32(sm);
    const uint32_t smb  = (smb0 + 127u) & ~127u;
    char* smc = sm + (smb - smb0);
    const uint32_t whHi = smb;                 /* 64KB: 32 rows x 2048B */
    const uint32_t whLo = smb + 65536u;        /* 64KB                  */
    const uint32_t hBuf = smb + 131072u;       /* 3 x 32KB ring         */

    const int tid  = threadIdx.x;
    const int lane = tid & 31;
    const int w    = tid >> 5;
    const int wm   = w & 1;                    /* m16 block (rows)      */
    const int wq   = w >> 1;                   /* n8 block (cols)       */
    const int jt   = blockIdx.x & 31, bt = blockIdx.x >> 5;
    const int j0   = jt * 32, b0 = bt * 32;

    /* ---- prologue: split Wh slice into SMEM hi/lo (swizzled) ---- */
#pragma unroll
    for (int i = 0; i < 32; i++) {
        int e4  = tid + i * 256;               /* float4 id, 0..8191    */
        int row = e4 >> 8;                     /* 0..31                 */
        int k4  = e4 & 255;
        float4 v = *(const float4*)(Wh + (size_t)(j0 + row) * DH + k4 * 4);
        __nv_bfloat162 h01, h23, l01, l23;
        split1(v.x, &h01.x, &l01.x); split1(v.y, &h01.y, &l01.y);
        split1(v.z, &h23.x, &l23.x); split1(v.w, &h23.y, &l23.y);
        uint32_t off = (uint32_t)row * 2048u
                     + (uint32_t)((((k4 >> 1) ^ (row & 7))) << 4)
                     + (uint32_t)(k4 & 1) * 8u;
        *(__nv_bfloat162*)(smc + off)           = h01;
        *(__nv_bfloat162*)(smc + off + 4)       = h23;
        *(__nv_bfloat162*)(smc + 65536 + off)     = l01;
        *(__nv_bfloat162*)(smc + 65536 + off + 4) = l23;
    }

    const int colb = j0 + wq * 8 + (lane & 3) * 2;
    const float whb0 = bh[colb], whb1 = bh[colb + 1];

    /* zero initial hidden state buffers (hi & lo, buffer 0) */
    if (tid < 128)
        ((uint4*)g_hhi[0])[blockIdx.x * 128 + tid] = make_uint4(0, 0, 0, 0);
    else
        ((uint4*)g_hlo[0])[blockIdx.x * 128 + (tid - 128)] = make_uint4(0, 0, 0, 0);

    {   /* initial full grid barrier */
        __syncthreads();
        if (threadIdx.x == 0) {
            volatile unsigned int* genp = (volatile unsigned int*)&g_gen;
            unsigned int g = *genp;
            __threadfence();
            unsigned int old = atomicAdd(&g_cnt, 1u);
            if (old == (unsigned)(SCTA - 1)) {
                g_cnt = 0; __threadfence(); atomicAdd(&g_gen, 1u);
            } else {
                while (*genp == g) { __nanosleep(64); }
            }
            __threadfence();
        }
        __syncthreads();
    }

/* H chunk: k=256, hi 16KB + lo 16KB = 32KB; row stride 512B */
#define LOAD_H(kc, bi, cur_) do {                                           \
    uint32_t _dbase = hBuf + (uint32_t)(bi) * 32768u;                       \
    _Pragma("unroll")                                                       \
    for (int _i = 0; _i < 8; _i++) {                                        \
        int _g  = tid + _i * 256;                                           \
        int _sp = _g >> 10, _rm = _g & 1023, _row = _rm >> 5, _kg = _rm & 31;\
        uint32_t _dst = _dbase + (uint32_t)_sp * 16384u                     \
                      + (uint32_t)_row * 512u                               \
                      + (uint32_t)((_kg ^ (_row & 7)) << 4);                \
        const __nv_bfloat16* _src = (_sp ? g_hlo[cur_] : g_hhi[cur_])       \
            + (size_t)(b0 + _row) * DH + (kc) * 256 + _kg * 8;              \
        CP16(_dst, _src);                                                   \
    }                                                                       \
    CP_COMMIT();                                                            \
} while (0)

    const int  arow = wm * 16 + (lane & 15);
    const int  axor = arow & 7;
    const int  ahlf = lane >> 4;
    const uint32_t aoffB = (uint32_t)arow * 512u;
    const int  l2   = lane & 15;
    const int  brow = wq * 8 + (l2 & 7);
    const int  bxor = brow & 7;
    const int  bhlf = (l2 >> 3) & 1;
    const uint32_t bbase = ((lane < 16) ? whHi : whLo) + (uint32_t)brow * 2048u;

    const int rl = lane >> 2;
    volatile unsigned int* genp = (volatile unsigned int*)&g_gen;

    for (int t = 0; t < T_; t++) {
        const int cur = t & 1;

        /* prefetch xs for this step (DRAM latency hidden behind MMA) */
        float2 x0, x1;
        {
            int bg0 = b0 + wm * 16 + rl;
            size_t mr = (size_t)t * 128 + bg0;
            x0 = *(const float2*)(g_xs + mr * DH + colb);
            x1 = *(const float2*)(g_xs + (mr + 8) * DH + colb);
        }

        LOAD_H(0, 0, cur);
        LOAD_H(1, 1, cur);

        float dhh[4] = {0.f, 0.f, 0.f, 0.f};
        float dhl[4] = {0.f, 0.f, 0.f, 0.f};
        float dlh[4] = {0.f, 0.f, 0.f, 0.f};

#pragma unroll
        for (int kc = 0; kc < 4; kc++) {
            if (kc < 3) CP_WAIT1(); else CP_WAIT0();
            __syncthreads();
            if (kc < 2) LOAD_H(kc + 2, (kc + 2) % 3, cur);  /* ring: chunk 2->slot 2, chunk 3->slot 0 */
            const uint32_t hb = hBuf + (uint32_t)(kc % 3) * 32768u;
#pragma unroll
            for (int k16l = 0; k16l < 16; k16l++) {
                uint32_t ah[4], al[4], bb[4];
                uint32_t ao = hb + aoffB
                            + (uint32_t)(((k16l * 2 + ahlf) ^ axor) << 4);
                ldsm4(ah, ao);
                ldsm4(al, ao + 16384u);
                uint32_t bo = bbase
                    + (uint32_t)((((kc * 16 + k16l) * 2 + bhlf) ^ bxor) << 4);
                ldsm4(bb, bo);                 /* {hi k8lo, hi k8hi, lo k8lo, lo k8hi} */
                mma16816(dhh, ah, bb);         /* independent accumulators */
                mma16816(dhl, ah, bb + 2);
                mma16816(dlh, al, bb);
            }
        }

        /* s = sum of products + bias + xs ; h' = tanh(s) */
        float s00 = dhh[0] + dhl[0] + dlh[0] + whb0 + x0.x;
        float s01 = dhh[1] + dhl[1] + dlh[1] + whb1 + x0.y;
        float s10 = dhh[2] + dhl[2] + dlh[2] + whb0 + x1.x;
        float s11 = dhh[3] + dhl[3] + dlh[3] + whb1 + x1.y;

        /* store next hidden state (needed by other CTAs) first */
        {
            int bg0 = b0 + wm * 16 + rl;
            __nv_bfloat162 hh, hl;
            float h0 = tanhf(s00), h1 = tanhf(s01);
            split1(h0, &hh.x, &hl.x); split1(h1, &hh.y, &hl.y);
            *(__nv_bfloat162*)(g_hhi[(t + 1) & 1] + (size_t)bg0 * DH + colb) = hh;
            *(__nv_bfloat162*)(g_hlo[(t + 1) & 1] + (size_t)bg0 * DH + colb) = hl;
            h0 = tanhf(s10); h1 = tanhf(s11);
            split1(h0, &hh.x, &hl.x); split1(h1, &hh.y, &hl.y);
            *(__nv_bfloat162*)(g_hhi[(t + 1) & 1] + (size_t)(bg0 + 8) * DH + colb) = hh;
            *(__nv_bfloat162*)(g_hlo[(t + 1) & 1] + (size_t)(bg0 + 8) * DH + colb) = hl;
        }

        /* split-phase grid barrier: arrive, do private s-stores, wait */
        __syncthreads();
        unsigned int gsnap = 0;
        if (tid == 0) {
            gsnap = *genp;
            __threadfence();
            unsigned int old = atomicAdd(&g_cnt, 1u);
            if (old == (unsigned)(SCTA - 1)) {
                g_cnt = 0; __threadfence(); atomicAdd(&g_gen, 1u);
            }
        }
        {   /* s hi/lo stores — private to this CTA, hide barrier wait */
            int bg0 = b0 + wm * 16 + rl;
            size_t mr = (size_t)t * 128 + bg0;
            __nv_bfloat162 hi2, lo2;
            split1(s00, &hi2.x, &lo2.x); split1(s01, &hi2.y, &lo2.y);
            *(__nv_bfloat162*)(g_shi + mr * DH + colb) = hi2;
            *(__nv_bfloat162*)(g_slo + mr * DH + colb) = lo2;
            split1(s10, &hi2.x, &lo2.x); split1(s11, &hi2.y, &lo2.y);
            *(__nv_bfloat162*)(g_shi + (mr + 8) * DH + colb) = hi2;
            *(__nv_bfloat162*)(g_slo + (mr + 8) * DH + colb) = lo2;
        }
        if (tid == 0) {
            while (*genp == gsnap) { __nanosleep(32); }
            __threadfence();
        }
        __syncthreads();
    }
#undef LOAD_H
}

/* ------------------------------------------------------------------ */
extern "C" void kernel_launch(void* const* d_in, const int* in_sizes, int n_in,
                              void* d_out, int out_size)
{
    const float* seq = (const float*)d_in[0];
    const float* Whw = (const float*)d_in[1];
    const float* Whb = (const float*)d_in[2];
    const float* Wxw = (const float*)d_in[3];
    const float* Wxb = (const float*)d_in[4];
    const float* Wow = (const float*)d_in[5];
    const float* Wob = (const float*)d_in[6];
    float* out = (float*)d_out;

    const int gemm_smem = 2 * 65536 + 1024;
    cudaFuncSetAttribute(wm_gemm<0>,
                         cudaFuncAttributeMaxDynamicSharedMemorySize, gemm_smem);
    cudaFuncSetAttribute(wm_gemm<1>,
                         cudaFuncAttributeMaxDynamicSharedMemorySize, gemm_smem);
    const int scan_smem = 131072 + 3 * 32768 + 128;   /* 229504 */
    cudaFuncSetAttribute(scan_mma,
                         cudaFuncAttributeMaxDynamicSharedMemorySize, scan_smem);

    zero_front<<<512, 256>>>(out);
    conv_seq<<<(B_ * T_ * DIN + 255) / 256, 256>>>(seq);
    conv_wx <<<(DH * DIN + 255) / 256, 256>>>(Wxw);
    conv_wo <<<(DOUT * DH + 255) / 256, 256>>>(Wow);

    wm_gemm<0><<<dim3(8, T_), 256, gemm_smem>>>(Wxb, nullptr);   /* xs */
    scan_mma<<<SCTA, 256, scan_smem>>>(Whw, Whb);
    wm_gemm<1><<<dim3(8, T_), 256, gemm_smem>>>(Wob, out);       /* o  */
}

// round 15
// speedup vs baseline: 1.0071x; 1.0071x over previous
#include <cuda_runtime.h>
#include <cuda_bf16.h>
#include <math.h>
#include <stdint.h>

#define B_   128
#define T_   512
#define DIN  256
#define DH   1024
#define DOUT 1024
#define BDH  (B_*DH)            /* 131072 */
#define OROW ((T_+1)*DOUT)      /* 525312 */
#define SCTA 128                /* persistent scan CTAs */

/* ------------------------------------------------------------------ */
/* Scratch (device globals: allocation-free rule)                      */
/* ------------------------------------------------------------------ */
__device__ float         g_xs  [(size_t)T_ * B_ * DH];   /* xs + Wx_b fp32  256MB */
__device__ __nv_bfloat16 g_shi [(size_t)T_ * B_ * DH];   /* s hi split      128MB */
__device__ __nv_bfloat16 g_slo [(size_t)T_ * B_ * DH];   /* s lo split      128MB */
__device__ __nv_bfloat16 g_seqhi[(size_t)B_ * T_ * DIN];
__device__ __nv_bfloat16 g_seqlo[(size_t)B_ * T_ * DIN];
__device__ __nv_bfloat16 g_wohi[(size_t)DOUT * DH];
__device__ __nv_bfloat16 g_wolo[(size_t)DOUT * DH];
__device__ __nv_bfloat16 g_wxhi[(size_t)DH * DIN];
__device__ __nv_bfloat16 g_wxlo[(size_t)DH * DIN];
__device__ __nv_bfloat16 g_hhi[2][BDH];       /* hidden state hi, ping-pong */
__device__ __nv_bfloat16 g_hlo[2][BDH];       /* hidden state lo            */
__device__ unsigned int g_cnt = 0;
__device__ unsigned int g_gen = 0;

/* ------------------------------------------------------------------ */
/* PTX helpers (all baseline ISA: valid for compute_103 / sm_103)      */
/* ------------------------------------------------------------------ */
__device__ __forceinline__ uint32_t smem_u32(const void* p) {
    uint32_t a;
    asm("{ .reg .u64 t; cvta.to.shared.u64 t, %1; cvt.u32.u64 %0, t; }"
        : "=r"(a) : "l"(p));
    return a;
}
__device__ __forceinline__ void ldsm4(uint32_t* r, uint32_t addr) {
    asm volatile("ldmatrix.sync.aligned.m8n8.x4.shared.b16 {%0,%1,%2,%3}, [%4];"
        : "=r"(r[0]), "=r"(r[1]), "=r"(r[2]), "=r"(r[3]) : "r"(addr));
}
__device__ __forceinline__ void mma16816(float* d, const uint32_t* a,
                                         const uint32_t* b) {
    asm volatile(
        "mma.sync.aligned.m16n8k16.row.col.f32.bf16.bf16.f32 "
        "{%0,%1,%2,%3}, {%4,%5,%6,%7}, {%8,%9}, {%0,%1,%2,%3};"
        : "+f"(d[0]), "+f"(d[1]), "+f"(d[2]), "+f"(d[3])
        : "r"(a[0]), "r"(a[1]), "r"(a[2]), "r"(a[3]), "r"(b[0]), "r"(b[1]));
}
#define CP16(dst, src) \
    asm volatile("cp.async.cg.shared.global [%0], [%1], 16;" :: "r"(dst), "l"(src))
#define CP_COMMIT()  asm volatile("cp.async.commit_group;" ::: "memory")
#define CP_WAIT0()   asm volatile("cp.async.wait_group 0;" ::: "memory")
#define CP_WAIT1()   asm volatile("cp.async.wait_group 1;" ::: "memory")

/* ------------------------------------------------------------------ */
__global__ void zero_front(float* __restrict__ out)
{
    int idx = blockIdx.x * blockDim.x + threadIdx.x;   /* 0 .. 131071 */
    int b = idx >> 10;
    int j = idx & 1023;
    out[(size_t)b * OROW + j] = 0.0f;
}

/* hi/lo bf16 split conversions */
__device__ __forceinline__ void split1(float x, __nv_bfloat16* hi, __nv_bfloat16* lo)
{
    __nv_bfloat16 h = __float2bfloat16(x);
    *hi = h;
    *lo = __float2bfloat16(x - __bfloat162float(h));
}
__global__ void conv_seq(const float* __restrict__ src)
{
    size_t i = (size_t)blockIdx.x * blockDim.x + threadIdx.x;
    if (i < (size_t)B_ * T_ * DIN) split1(src[i], &g_seqhi[i], &g_seqlo[i]);
}
__global__ void conv_wo(const float* __restrict__ src)
{
    size_t i = (size_t)blockIdx.x * blockDim.x + threadIdx.x;
    if (i < (size_t)DOUT * DH) split1(src[i], &g_wohi[i], &g_wolo[i]);
}
__global__ void conv_wx(const float* __restrict__ src)
{
    size_t i = (size_t)blockIdx.x * blockDim.x + threadIdx.x;
    if (i < (size_t)DH * DIN) split1(src[i], &g_wxhi[i], &g_wxlo[i]);
}

/* ------------------------------------------------------------------ */
/* mma.sync GEMM (unchanged, proven):                                  */
/* MODE 0: xs  = seq @ Wx^T + bx   (K=256)  -> g_xs fp32               */
/* MODE 1: out = s   @ Wo^T + bo   (K=1024) -> scattered into d_out    */
/* ------------------------------------------------------------------ */
template<int MODE>
__global__ __launch_bounds__(256) void wm_gemm(const float* __restrict__ bias,
                                               float* __restrict__ outp)
{
    constexpr int K  = (MODE == 0) ? DIN : DH;
    constexpr int NC = K / 64;

    extern __shared__ char sm[];
    const uint32_t smb = (smem_u32(sm) + 1023u) & ~1023u;

    const int tid  = threadIdx.x;
    const int lane = tid & 31;
    const int w    = tid >> 5;
    const int wm   = w & 3;
    const int wn   = w >> 2;
    const int n0   = blockIdx.x * 128;
    const int tY   = blockIdx.y;
    const int m0   = tY * 128;

    const __nv_bfloat16* Ahi_g;
    const __nv_bfloat16* Alo_g;
    const __nv_bfloat16* Bhi_g;
    const __nv_bfloat16* Blo_g;
    if (MODE == 0) { Ahi_g = g_seqhi; Alo_g = g_seqlo; Bhi_g = g_wxhi; Blo_g = g_wxlo; }
    else           { Ahi_g = g_shi;   Alo_g = g_slo;   Bhi_g = g_wohi; Blo_g = g_wolo; }

#define LOAD_CHUNK(cc, bb_) do {                                            \
    uint32_t _db = smb + (uint32_t)(bb_) * 65536u;                          \
    _Pragma("unroll")                                                       \
    for (int _i = 0; _i < 16; _i++) {                                       \
        int _tile = _i >> 2;                                                \
        int _r    = (_i & 3) * 32 + (tid >> 3);                             \
        int _c16  = tid & 7;                                                \
        uint32_t _dst = _db + (uint32_t)_tile * 16384u + (uint32_t)_r * 128u\
                      + (uint32_t)((_c16 ^ (_r & 7)) << 4);                 \
        const __nv_bfloat16* _src;                                          \
        if (_tile == 0 || _tile == 1) {                                     \
            const __nv_bfloat16* _A = (_tile == 0) ? Ahi_g : Alo_g;         \
            if (MODE == 0)                                                  \
                _src = _A + ((size_t)_r * T_ + tY) * DIN + _c16 * 8 + (cc) * 64; \
            else                                                            \
                _src = _A + (size_t)(m0 + _r) * DH + _c16 * 8 + (cc) * 64;  \
        } else {                                                            \
            const __nv_bfloat16* _B = (_tile == 2) ? Bhi_g : Blo_g;         \
            _src = _B + (size_t)(n0 + _r) * K + _c16 * 8 + (cc) * 64;       \
        }                                                                   \
        CP16(_dst, _src);                                                   \
    }                                                                       \
    CP_COMMIT();                                                            \
} while (0)

    const int arow = wm * 32 + (lane & 15);
    const int axor = arow & 7;
    const int ahlf = lane >> 4;
    const int brow = wn * 64 + ((lane >> 4) & 1) * 8 + (lane & 7);
    const int bxor = brow & 7;
    const int bhlf = (lane >> 3) & 1;

    float d[64];
#pragma unroll
    for (int i = 0; i < 64; i++) d[i] = 0.f;

    LOAD_CHUNK(0, 0);

    for (int c = 0; c < NC; c++) {
        if (c + 1 < NC) LOAD_CHUNK(c + 1, (c + 1) & 1);
        if (c + 1 < NC) CP_WAIT1(); else CP_WAIT0();
        __syncthreads();

        const uint32_t db = smb + (uint32_t)(c & 1) * 65536u;
#pragma unroll
        for (int k16 = 0; k16 < 4; k16++) {
            uint32_t ahi[8], alo[8], bb[16];
            const uint32_t ao = db + (uint32_t)arow * 128u
                              + (uint32_t)(((k16 * 2 + ahlf) ^ axor) << 4);
            ldsm4(ahi,     ao);
            ldsm4(ahi + 4, ao + 2048u);
            const uint32_t bo = db + 32768u + (uint32_t)brow * 128u
                              + (uint32_t)(((k16 * 2 + bhlf) ^ bxor) << 4);
#pragma unroll
            for (int p = 0; p < 4; p++) ldsm4(bb + p * 4, bo + (uint32_t)p * 2048u);
#pragma unroll
            for (int t = 0; t < 2; t++)
#pragma unroll
                for (int q = 0; q < 8; q++)
                    mma16816(d + (t * 8 + q) * 4, ahi + t * 4, bb + q * 2);

            ldsm4(alo,     ao + 16384u);
            ldsm4(alo + 4, ao + 16384u + 2048u);
#pragma unroll
            for (int t = 0; t < 2; t++)
#pragma unroll
                for (int q = 0; q < 8; q++)
                    mma16816(d + (t * 8 + q) * 4, alo + t * 4, bb + q * 2);

#pragma unroll
            for (int p = 0; p < 4; p++)
                ldsm4(bb + p * 4, bo + 16384u + (uint32_t)p * 2048u);
#pragma unroll
            for (int t = 0; t < 2; t++)
#pragma unroll
                for (int q = 0; q < 8; q++)
                    mma16816(d + (t * 8 + q) * 4, ahi + t * 4, bb + q * 2);
        }
        __syncthreads();
    }

    const int rl = lane >> 2;
    const int lc = (lane & 3) * 2;
#pragma unroll
    for (int t = 0; t < 2; t++)
#pragma unroll
        for (int q = 0; q < 8; q++) {
            int col = n0 + wn * 64 + q * 8 + lc;
            float b0v = __ldg(bias + col), b1v = __ldg(bias + col + 1);
            float* dd = d + (t * 8 + q) * 4;
            int r0 = wm * 32 + t * 16 + rl;
            if (MODE == 0) {
                *(float2*)(g_xs + (size_t)(m0 + r0) * DH + col) =
                    make_float2(dd[0] + b0v, dd[1] + b1v);
                *(float2*)(g_xs + (size_t)(m0 + r0 + 8) * DH + col) =
                    make_float2(dd[2] + b0v, dd[3] + b1v);
            } else {
                *(float2*)(outp + (size_t)r0 * OROW + (size_t)(tY + 1) * DOUT + col) =
                    make_float2(dd[0] + b0v, dd[1] + b1v);
                *(float2*)(outp + (size_t)(r0 + 8) * OROW + (size_t)(tY + 1) * DOUT + col) =
                    make_float2(dd[2] + b0v, dd[3] + b1v);
            }
        }
#undef LOAD_CHUNK
}

/* ------------------------------------------------------------------ */
/* Persistent tensorized scan, v2 (ring-slot fix: chunk 3 -> slot 0).  */
/*  - 3 independent accumulators (break HMMA RAW chain)                */
/*  - k=256 chunks, 3-stage cp.async ring -> 4 syncthreads/step        */
/*  - B hi+lo fused into one ldsm4 (lane-split whHi/whLo)              */
/*  - xs prefetched at step start; split-phase grid barrier with       */
/*    s hi/lo stores inside the wait window                            */
/* SMEM: Wh hi 64KB | Wh lo 64KB | 3 x 32KB H ring = 224KB             */
/* ------------------------------------------------------------------ */
__global__ __launch_bounds__(256) void scan_mma(const float* __restrict__ Wh,
                                                const float* __restrict__ bh)
{
    extern __shared__ char sm[];
    const uint32_t smb0 = smem_u32(sm);
    const uint32_t smb  = (smb0 + 127u) & ~127u;
    char* smc = sm + (smb - smb0);
    const uint32_t whHi = smb;                 /* 64KB: 32 rows x 2048B */
    const uint32_t whLo = smb + 65536u;        /* 64KB                  */
    const uint32_t hBuf = smb + 131072u;       /* 3 x 32KB ring         */

    const int tid  = threadIdx.x;
    const int lane = tid & 31;
    const int w    = tid >> 5;
    const int wm   = w & 1;                    /* m16 block (rows)      */
    const int wq   = w >> 1;                   /* n8 block (cols)       */
    const int jt   = blockIdx.x & 31, bt = blockIdx.x >> 5;
    const int j0   = jt * 32, b0 = bt * 32;

    /* ---- prologue: split Wh slice into SMEM hi/lo (swizzled) ---- */
#pragma unroll
    for (int i = 0; i < 32; i++) {
        int e4  = tid + i * 256;               /* float4 id, 0..8191    */
        int row = e4 >> 8;                     /* 0..31                 */
        int k4  = e4 & 255;
        float4 v = *(const float4*)(Wh + (size_t)(j0 + row) * DH + k4 * 4);
        __nv_bfloat162 h01, h23, l01, l23;
        split1(v.x, &h01.x, &l01.x); split1(v.y, &h01.y, &l01.y);
        split1(v.z, &h23.x, &l23.x); split1(v.w, &h23.y, &l23.y);
        uint32_t off = (uint32_t)row * 2048u
                     + (uint32_t)((((k4 >> 1) ^ (row & 7))) << 4)
                     + (uint32_t)(k4 & 1) * 8u;
        *(__nv_bfloat162*)(smc + off)           = h01;
        *(__nv_bfloat162*)(smc + off + 4)       = h23;
        *(__nv_bfloat162*)(smc + 65536 + off)     = l01;
        *(__nv_bfloat162*)(smc + 65536 + off + 4) = l23;
    }

    const int colb = j0 + wq * 8 + (lane & 3) * 2;
    const float whb0 = bh[colb], whb1 = bh[colb + 1];

    /* zero initial hidden state buffers (hi & lo, buffer 0) */
    if (tid < 128)
        ((uint4*)g_hhi[0])[blockIdx.x * 128 + tid] = make_uint4(0, 0, 0, 0);
    else
        ((uint4*)g_hlo[0])[blockIdx.x * 128 + (tid - 128)] = make_uint4(0, 0, 0, 0);

    {   /* initial full grid barrier */
        __syncthreads();
        if (threadIdx.x == 0) {
            volatile unsigned int* genp = (volatile unsigned int*)&g_gen;
            unsigned int g = *genp;
            __threadfence();
            unsigned int old = atomicAdd(&g_cnt, 1u);
            if (old == (unsigned)(SCTA - 1)) {
                g_cnt = 0; __threadfence(); atomicAdd(&g_gen, 1u);
            } else {
                while (*genp == g) { __nanosleep(64); }
            }
            __threadfence();
        }
        __syncthreads();
    }

/* H chunk: k=256, hi 16KB + lo 16KB = 32KB; row stride 512B */
#define LOAD_H(kc, bi, cur_) do {                                           \
    uint32_t _dbase = hBuf + (uint32_t)(bi) * 32768u;                       \
    _Pragma("unroll")                                                       \
    for (int _i = 0; _i < 8; _i++) {                                        \
        int _g  = tid + _i * 256;                                           \
        int _sp = _g >> 10, _rm = _g & 1023, _row = _rm >> 5, _kg = _rm & 31;\
        uint32_t _dst = _dbase + (uint32_t)_sp * 16384u                     \
                      + (uint32_t)_row * 512u                               \
                      + (uint32_t)((_kg ^ (_row & 7)) << 4);                \
        const __nv_bfloat16* _src = (_sp ? g_hlo[cur_] : g_hhi[cur_])       \
            + (size_t)(b0 + _row) * DH + (kc) * 256 + _kg * 8;              \
        CP16(_dst, _src);                                                   \
    }                                                                       \
    CP_COMMIT();                                                            \
} while (0)

    const int  arow = wm * 16 + (lane & 15);
    const int  axor = arow & 7;
    const int  ahlf = lane >> 4;
    const uint32_t aoffB = (uint32_t)arow * 512u;
    const int  l2   = lane & 15;
    const int  brow = wq * 8 + (l2 & 7);
    const int  bxor = brow & 7;
    const int  bhlf = (l2 >> 3) & 1;
    const uint32_t bbase = ((lane < 16) ? whHi : whLo) + (uint32_t)brow * 2048u;

    const int rl = lane >> 2;
    volatile unsigned int* genp = (volatile unsigned int*)&g_gen;

    for (int t = 0; t < T_; t++) {
        const int cur = t & 1;

        /* prefetch xs for this step (DRAM latency hidden behind MMA) */
        float2 x0, x1;
        {
            int bg0 = b0 + wm * 16 + rl;
            size_t mr = (size_t)t * 128 + bg0;
            x0 = *(const float2*)(g_xs + mr * DH + colb);
            x1 = *(const float2*)(g_xs + (mr + 8) * DH + colb);
        }

        LOAD_H(0, 0, cur);
        LOAD_H(1, 1, cur);

        float dhh[4] = {0.f, 0.f, 0.f, 0.f};
        float dhl[4] = {0.f, 0.f, 0.f, 0.f};
        float dlh[4] = {0.f, 0.f, 0.f, 0.f};

#pragma unroll
        for (int kc = 0; kc < 4; kc++) {
            if (kc < 3) CP_WAIT1(); else CP_WAIT0();
            __syncthreads();
            if (kc < 2) LOAD_H(kc + 2, (kc + 2) % 3, cur);  /* ring: chunk 2->slot 2, chunk 3->slot 0 */
            const uint32_t hb = hBuf + (uint32_t)(kc % 3) * 32768u;
#pragma unroll
            for (int k16l = 0; k16l < 16; k16l++) {
                uint32_t ah[4], al[4], bb[4];
                uint32_t ao = hb + aoffB
                            + (uint32_t)(((k16l * 2 + ahlf) ^ axor) << 4);
                ldsm4(ah, ao);
                ldsm4(al, ao + 16384u);
                uint32_t bo = bbase
                    + (uint32_t)((((kc * 16 + k16l) * 2 + bhlf) ^ bxor) << 4);
                ldsm4(bb, bo);                 /* {hi k8lo, hi k8hi, lo k8lo, lo k8hi} */
                mma16816(dhh, ah, bb);         /* independent accumulators */
                mma16816(dhl, ah, bb + 2);
                mma16816(dlh, al, bb);
            }
        }

        /* s = sum of products + bias + xs ; h' = tanh(s) */
        float s00 = dhh[0] + dhl[0] + dlh[0] + whb0 + x0.x;
        float s01 = dhh[1] + dhl[1] + dlh[1] + whb1 + x0.y;
        float s10 = dhh[2] + dhl[2] + dlh[2] + whb0 + x1.x;
        float s11 = dhh[3] + dhl[3] + dlh[3] + whb1 + x1.y;

        /* store next hidden state (needed by other CTAs) first */
        {
            int bg0 = b0 + wm * 16 + rl;
            __nv_bfloat162 hh, hl;
            float h0 = tanhf(s00), h1 = tanhf(s01);
            split1(h0, &hh.x, &hl.x); split1(h1, &hh.y, &hl.y);
            *(__nv_bfloat162*)(g_hhi[(t + 1) & 1] + (size_t)bg0 * DH + colb) = hh;
            *(__nv_bfloat162*)(g_hlo[(t + 1) & 1] + (size_t)bg0 * DH + colb) = hl;
            h0 = tanhf(s10); h1 = tanhf(s11);
            split1(h0, &hh.x, &hl.x); split1(h1, &hh.y, &hl.y);
            *(__nv_bfloat162*)(g_hhi[(t + 1) & 1] + (size_t)(bg0 + 8) * DH + colb) = hh;
            *(__nv_bfloat162*)(g_hlo[(t + 1) & 1] + (size_t)(bg0 + 8) * DH + colb) = hl;
        }

        /* split-phase grid barrier: arrive, do private s-stores, wait */
        __syncthreads();
        unsigned int gsnap = 0;
        if (tid == 0) {
            gsnap = *genp;
            __threadfence();
            unsigned int old = atomicAdd(&g_cnt, 1u);
            if (old == (unsigned)(SCTA - 1)) {
                g_cnt = 0; __threadfence(); atomicAdd(&g_gen, 1u);
            }
        }
        {   /* s hi/lo stores — private to this CTA, hide barrier wait */
            int bg0 = b0 + wm * 16 + rl;
            size_t mr = (size_t)t * 128 + bg0;
            __nv_bfloat162 hi2, lo2;
            split1(s00, &hi2.x, &lo2.x); split1(s01, &hi2.y, &lo2.y);
            *(__nv_bfloat162*)(g_shi + mr * DH + colb) = hi2;
            *(__nv_bfloat162*)(g_slo + mr * DH + colb) = lo2;
            split1(s10, &hi2.x, &lo2.x); split1(s11, &hi2.y, &lo2.y);
            *(__nv_bfloat162*)(g_shi + (mr + 8) * DH + colb) = hi2;
            *(__nv_bfloat162*)(g_slo + (mr + 8) * DH + colb) = lo2;
        }
        if (tid == 0) {
            while (*genp == gsnap) { __nanosleep(32); }
            __threadfence();
        }
        __syncthreads();
    }
#undef LOAD_H
}

/* ------------------------------------------------------------------ */
extern "C" void kernel_launch(void* const* d_in, const int* in_sizes, int n_in,
                              void* d_out, int out_size)
{
    const float* seq = (const float*)d_in[0];
    const float* Whw = (const float*)d_in[1];
    const float* Whb = (const float*)d_in[2];
    const float* Wxw = (const float*)d_in[3];
    const float* Wxb = (const float*)d_in[4];
    const float* Wow = (const float*)d_in[5];
    const float* Wob = (const float*)d_in[6];
    float* out = (float*)d_out;

    const int gemm_smem = 2 * 65536 + 1024;
    cudaFuncSetAttribute(wm_gemm<0>,
                         cudaFuncAttributeMaxDynamicSharedMemorySize, gemm_smem);
    cudaFuncSetAttribute(wm_gemm<1>,
                         cudaFuncAttributeMaxDynamicSharedMemorySize, gemm_smem);
    const int scan_smem = 131072 + 3 * 32768 + 128;   /* 229504 */
    cudaFuncSetAttribute(scan_mma,
                         cudaFuncAttributeMaxDynamicSharedMemorySize, scan_smem);

    zero_front<<<512, 256>>>(out);
    conv_seq<<<(B_ * T_ * DIN + 255) / 256, 256>>>(seq);
    conv_wx <<<(DH * DIN + 255) / 256, 256>>>(Wxw);
    conv_wo <<<(DOUT * DH + 255) / 256, 256>>>(Wow);

    wm_gemm<0><<<dim3(8, T_), 256, gemm_smem>>>(Wxb, nullptr);   /* xs */
    scan_mma<<<SCTA, 256, scan_smem>>>(Whw, Whb);
    wm_gemm<1><<<dim3(8, T_), 256, gemm_smem>>>(Wob, out);       /* o  */
}